// round 16
// baseline (speedup 1.0000x reference)
#include <cuda_runtime.h>
#include <cuda_fp16.h>
#include <cstdint>
#include <cstddef>

#define NB 64
#define NC 256
#define NL 4096
#define LT 4

// ---------------- scratch (device globals; no allocation allowed) ----------
__device__ float d_M [NC * NC];                 // Wq^T Wk / sqrt(C)
__device__ float d_W2[NC * NC];                 // Wout @ Wc
__device__ float d_g   [(size_t)NB * NC * NL];  // M @ x
__device__ float d_v   [(size_t)NB * NC * NL];  // Wv @ x
__device__ __half d_virt_h[(size_t)NB * NC * NL];  // attention output (fp16)
__device__ float d_mean[NB];
__device__ float d_rstd[NB];
__device__ float d_pS[(NL / LT) * NB];          // per-CTA partial sums
__device__ float d_pQ[(NL / LT) * NB];
__device__ __half d_A0h[512 * 256];             // fp16([M ; Wv])
__device__ __half d_A1h[256 * 512];             // fp16([Wout | W2])
// unified fp16 B tensor: rows 0-255 = fp16(x); rows 256-511 = fp16(relu(gn(virt)))
__device__ __half d_xact_h[(size_t)NB * 512 * NL];

// ---------------- helpers ---------------------------------------------------
__device__ __forceinline__ void mma_f16(float* c, const uint32_t* a,
                                        const uint32_t* b) {
    asm volatile(
        "mma.sync.aligned.m16n8k16.row.col.f32.f16.f16.f32 "
        "{%0,%1,%2,%3}, {%4,%5,%6,%7}, {%8,%9}, {%0,%1,%2,%3};"
        : "+f"(c[0]), "+f"(c[1]), "+f"(c[2]), "+f"(c[3])
        : "r"(a[0]), "r"(a[1]), "r"(a[2]), "r"(a[3]), "r"(b[0]), "r"(b[1]));
}

// ---------------- K0: M = Wq^T Wk / 16 -------------------------------------
__global__ void k0_M(const float* __restrict__ Wq, const float* __restrict__ Wk) {
    __shared__ float sA[16][17], sB[16][17];
    int tx = threadIdx.x, ty = threadIdx.y;
    int c1 = blockIdx.y * 16 + ty;
    int c2 = blockIdx.x * 16 + tx;
    float acc = 0.f;
    for (int o0 = 0; o0 < NC; o0 += 16) {
        sA[ty][tx] = Wq[(o0 + ty) * NC + blockIdx.y * 16 + tx];
        sB[ty][tx] = Wk[(o0 + ty) * NC + blockIdx.x * 16 + tx];
        __syncthreads();
#pragma unroll
        for (int i = 0; i < 16; i++) acc += sA[i][ty] * sB[i][tx];
        __syncthreads();
    }
    d_M[c1 * NC + c2] = acc * 0.0625f;
}

// ---------------- K0b: W2 = Wout @ Wc --------------------------------------
__global__ void k0_W2(const float* __restrict__ Wout, const float* __restrict__ Wc) {
    __shared__ float sA[16][17], sB[16][17];
    int tx = threadIdx.x, ty = threadIdx.y;
    int o = blockIdx.y * 16 + ty;
    int c = blockIdx.x * 16 + tx;
    float acc = 0.f;
    for (int m0 = 0; m0 < NC; m0 += 16) {
        sA[ty][tx] = Wout[o * NC + m0 + tx];
        sB[ty][tx] = Wc[(m0 + ty) * NC + blockIdx.x * 16 + tx];
        __syncthreads();
#pragma unroll
        for (int i = 0; i < 16; i++) acc += sA[ty][i] * sB[i][tx];
        __syncthreads();
    }
    d_W2[o * NC + c] = acc;
}

// ---------------- prepass: A matrices -> fp16 -------------------------------
__global__ void kprep_Ah(const float* __restrict__ Wv, const float* __restrict__ Wout) {
    int i = blockIdx.x * 256 + threadIdx.x;          // 0..131071
    d_A0h[i] = __float2half((i < 65536) ? d_M[i] : Wv[i - 65536]);
    int r = i >> 9, k = i & 511;
    d_A1h[i] = __float2half((k < 256) ? Wout[r * 256 + k] : d_W2[r * 256 + (k - 256)]);
}

// ---------------- prepass: x -> fp16 rows [b][0..255][L] ---------------------
__global__ void kcvt_xh(const float* __restrict__ x) {
    size_t i = (size_t)blockIdx.x * 256 + threadIdx.x;   // float4 granule
    float4 v = ((const float4*)x)[i];
    size_t row = i >> 10;                 // b*256 + c   (NL/4 = 1024)
    size_t b = row >> 8, c = row & 255;
    uint2 u;
    *(__half2*)&u.x = __floats2half2_rn(v.x, v.y);
    *(__half2*)&u.y = __floats2half2_rn(v.z, v.w);
    *(uint2*)(d_xact_h + ((b * 512 + c) * NL) + (i & 1023) * 4) = u;
}

// ------- prepass: gn+relu(virt_h) -> fp16 rows [b][256..511][L] --------------
__global__ void kprep_act(const float* __restrict__ gamma, const float* __restrict__ beta) {
    size_t i = (size_t)blockIdx.x * 256 + threadIdx.x;   // uint2 granule
    size_t row = i >> 10;                 // b*256 + c
    int b = (int)(row >> 8), c = (int)(row & 255);
    float rs = d_rstd[b];
    float gsc = gamma[c] * rs;
    float bt  = beta[c] - d_mean[b] * gsc;
    uint2 u = *(uint2*)(d_virt_h + row * NL + (i & 1023) * 4);
    float2 p01 = __half22float2(*(__half2*)&u.x);
    float2 p23 = __half22float2(*(__half2*)&u.y);
    float v0 = fmaxf(fmaf(p01.x, gsc, bt), 0.f);
    float v1 = fmaxf(fmaf(p01.y, gsc, bt), 0.f);
    float v2 = fmaxf(fmaf(p23.x, gsc, bt), 0.f);
    float v3 = fmaxf(fmaf(p23.y, gsc, bt), 0.f);
    uint2 o;
    *(__half2*)&o.x = __floats2half2_rn(v0, v1);
    *(__half2*)&o.y = __floats2half2_rn(v2, v3);
    *(uint2*)(d_xact_h + (((size_t)b * 512 + 256 + c) * NL) + (i & 1023) * 4) = o;
}

// ---------------- FP16 tensor-core GEMM (specialized per mode) ---------------
// MODE 0: Y[512,L] = [M ; Wv] @ xh[b]         -> d_g / d_v   (K = 256)
// MODE 1: out[256,L] = [Wout|W2] @ xact[b]                   (K = 512)
// CTA tile 128(m) x 128(l), k-chunk 32, 8 warps (2m x 4n), warp tile 64x32.
// A + B register prefetch, double-buffered smem, one barrier per chunk.
template <int MODE>
__global__ __launch_bounds__(256, 2) void k_gemm(float* __restrict__ out) {
    constexpr int KST = MODE ? 512 : 256;
    constexpr int NCH = KST / 32;
    __shared__ __half  As[2][128][40];   // bank=(20g+tg)%32 bijective
    __shared__ __half2 Bs2[2][16][136];  // half2=(k even,k odd); bank=(8tg+g)%32

    int tid = threadIdx.x;
    int b   = blockIdx.z;
    int l0  = blockIdx.y * 128;
    int m0  = blockIdx.x * 128;
    const __half* Ah = (MODE ? d_A1h : d_A0h) + (size_t)m0 * KST;
    const __half* Bb = d_xact_h + (size_t)b * 512 * NL;

    float* Ybase;
    int mbase;
    if (MODE == 0) {
        if (m0 < 256) { Ybase = d_g; mbase = m0; }
        else          { Ybase = d_v; mbase = m0 - 256; }
    } else {
        Ybase = out; mbase = m0;
    }

    int lane = tid & 31, w = tid >> 5;
    int g = lane >> 2, tg = lane & 3;
    int wm = (w & 1) * 64, wn = (w >> 1) * 32;

    float acc[4][4][4];
#pragma unroll
    for (int mt = 0; mt < 4; mt++)
#pragma unroll
        for (int nt = 0; nt < 4; nt++)
#pragma unroll
            for (int i = 0; i < 4; i++) acc[mt][nt][i] = 0.f;

    // per-thread staging coordinates (fixed across chunks)
    int ar0 = tid >> 2,          as0 = (tid & 3) * 8;
    int ar1 = (tid + 256) >> 2,  as1 = (tid & 3) * 8;
    int k2_0 = tid >> 5,         cl0 = (tid & 31) * 4;
    int k2_1 = (tid + 256) >> 5, cl1 = (tid & 31) * 4;

    // ---- prefetch chunk 0 ----
    uint4 pa[2];
    uint2 pv[4];
    pa[0] = *(const uint4*)(Ah + (size_t)ar0 * KST + as0);
    pa[1] = *(const uint4*)(Ah + (size_t)ar1 * KST + as1);
    {
        const __half* B0 = Bb + (size_t)(2 * k2_0) * NL + l0 + cl0;
        const __half* B1 = Bb + (size_t)(2 * k2_1) * NL + l0 + cl1;
        pv[0] = *(const uint2*)B0;
        pv[1] = *(const uint2*)(B0 + NL);
        pv[2] = *(const uint2*)B1;
        pv[3] = *(const uint2*)(B1 + NL);
    }

#pragma unroll 1
    for (int ch = 0; ch < NCH; ch++) {
        int st = ch & 1;
        // ---- stage A from regs ----
        *(uint4*)&As[st][ar0][as0] = pa[0];
        *(uint4*)&As[st][ar1][as1] = pa[1];
        // ---- stage B from regs (repack l-vectors into k-pair half2) ----
#pragma unroll
        for (int j = 0; j < 2; j++) {
            int k2 = j ? k2_1 : k2_0;
            int cl = j ? cl1 : cl0;
            const __half* h0 = (const __half*)&pv[2 * j];
            const __half* h1 = (const __half*)&pv[2 * j + 1];
#pragma unroll
            for (int i = 0; i < 4; i++)
                Bs2[st][k2][cl + i] = __halves2half2(h0[i], h1[i]);
        }
        __syncthreads();

        // ---- issue prefetch for next chunk (latency overlaps compute) ----
        if (ch + 1 < NCH) {
            int kn = (ch + 1) * 32;
            pa[0] = *(const uint4*)(Ah + (size_t)ar0 * KST + kn + as0);
            pa[1] = *(const uint4*)(Ah + (size_t)ar1 * KST + kn + as1);
            const __half* B0 = Bb + (size_t)(kn + 2 * k2_0) * NL + l0 + cl0;
            const __half* B1 = Bb + (size_t)(kn + 2 * k2_1) * NL + l0 + cl1;
            pv[0] = *(const uint2*)B0;
            pv[1] = *(const uint2*)(B0 + NL);
            pv[2] = *(const uint2*)B1;
            pv[3] = *(const uint2*)(B1 + NL);
        }

        // ---- compute: 2 k16-steps x 16 mma ----
#pragma unroll
        for (int ks = 0; ks < 2; ks++) {
            int kb = ks * 16;
            int k2b = ks * 8;
            uint32_t bf[4][2];
#pragma unroll
            for (int nt = 0; nt < 4; nt++) {
                int n = wn + nt * 8 + g;
                bf[nt][0] = *(uint32_t*)&Bs2[st][k2b + tg][n];
                bf[nt][1] = *(uint32_t*)&Bs2[st][k2b + tg + 4][n];
            }
            uint32_t af[4][4];
#pragma unroll
            for (int mt = 0; mt < 4; mt++) {
                int rb = wm + mt * 16;
                af[mt][0] = *(uint32_t*)&As[st][rb + g][kb + 2 * tg];
                af[mt][1] = *(uint32_t*)&As[st][rb + g + 8][kb + 2 * tg];
                af[mt][2] = *(uint32_t*)&As[st][rb + g][kb + 2 * tg + 8];
                af[mt][3] = *(uint32_t*)&As[st][rb + g + 8][kb + 2 * tg + 8];
            }
#pragma unroll
            for (int mt = 0; mt < 4; mt++)
#pragma unroll
                for (int nt = 0; nt < 4; nt++)
                    mma_f16(acc[mt][nt], af[mt], bf[nt]);
        }
    }

    // ---- epilogue: fp32 stores ----
#pragma unroll
    for (int mt = 0; mt < 4; mt++) {
        int m = mbase + wm + mt * 16 + g;
        float* y0 = Ybase + ((size_t)b * NC + m) * NL + l0;
        float* y1 = Ybase + ((size_t)b * NC + m + 8) * NL + l0;
#pragma unroll
        for (int nt = 0; nt < 4; nt++) {
            int l = wn + nt * 8 + 2 * tg;
            y0[l]     = acc[mt][nt][0];
            y0[l + 1] = acc[mt][nt][1];
            y1[l]     = acc[mt][nt][2];
            y1[l + 1] = acc[mt][nt][3];
        }
    }
}

// ---------------- K2: attention per l-tile (LT=4), fused stats --------------
#define SP_STR  260
#define SX_STR  36
#define SV2_STR 260
#define PH_STR  260
#define K2_SMEM ((16640 + 8320) * 4)

__global__ __launch_bounds__(256, 2) void k2_attn(const float* __restrict__ x) {
    extern __shared__ float smemf[];
    float*  sP  = smemf;                       // [64][260] fp32 att
    float*  sX  = smemf + 16640;               // [64][36]
    float*  sG  = sX + 64 * SX_STR;            // [64][36]
    __half* sPh = (__half*)(smemf + 16640);    // [64][260] fp16 P (after phase 1)
    float*  sV  = smemf;                       // [64][260] V tile (phase 3)
    float*  sRS = smemf + 16640;               // [8][64] partial sums (after ph3)
    float*  sRQ = sRS + 512;

    int tid = threadIdx.x;
    int lt  = blockIdx.x * LT;
    int tb  = tid & 15;
    int td  = tid >> 4;

    // ---- phase 1: att[b,d,l] = sum_c x[b,c,l] * g[d,c,l] ----
    {
        float acc[4][4][4];
#pragma unroll
        for (int i = 0; i < 4; i++)
#pragma unroll
            for (int j = 0; j < 4; j++)
#pragma unroll
                for (int l = 0; l < 4; l++) acc[i][j][l] = 0.f;

        for (int c0 = 0; c0 < NC; c0 += 8) {
#pragma unroll
            for (int j = 0; j < 2; j++) {
                int t  = tid + j * 256;
                int bb = t >> 3, cc = t & 7;
                *(float4*)&sX[bb * SX_STR + cc * 4] =
                    *(const float4*)(x   + ((size_t)bb * NC + c0 + cc) * NL + lt);
                *(float4*)&sG[bb * SX_STR + cc * 4] =
                    *(const float4*)(d_g + ((size_t)bb * NC + c0 + cc) * NL + lt);
            }
            __syncthreads();
#pragma unroll
            for (int cc = 0; cc < 8; cc++) {
                float4 xv[4], gv[4];
#pragma unroll
                for (int i = 0; i < 4; i++)
                    xv[i] = *(float4*)&sX[(tb + 16 * i) * SX_STR + cc * 4];
#pragma unroll
                for (int i = 0; i < 4; i++)
                    gv[i] = *(float4*)&sG[(td + 16 * i) * SX_STR + cc * 4];
#pragma unroll
                for (int bi = 0; bi < 4; bi++)
#pragma unroll
                    for (int di = 0; di < 4; di++) {
                        acc[bi][di][0] += xv[bi].x * gv[di].x;
                        acc[bi][di][1] += xv[bi].y * gv[di].y;
                        acc[bi][di][2] += xv[bi].z * gv[di].z;
                        acc[bi][di][3] += xv[bi].w * gv[di].w;
                    }
            }
            __syncthreads();
        }
#pragma unroll
        for (int bi = 0; bi < 4; bi++)
#pragma unroll
            for (int di = 0; di < 4; di++)
#pragma unroll
                for (int l = 0; l < 4; l++)
                    sP[(tb + 16 * bi) * SP_STR + (td + 16 * di) * 4 + l] = acc[bi][di][l];
        __syncthreads();
    }

    // ---- phase 2: softmax over d; write P as fp16 into sPh ----
    {
        int b = tid >> 2, l = tid & 3;
        float* row = sP + b * SP_STR + l;
        float mx = -1e30f;
#pragma unroll 8
        for (int d = 0; d < 64; d++) mx = fmaxf(mx, row[d * 4]);
        float s = 0.f;
        float e_[64];
#pragma unroll 8
        for (int d = 0; d < 64; d++) {
            float e = __expf(row[d * 4] - mx);
            e_[d] = e;
            s += e;
        }
        float inv = 1.f / s;
        __syncthreads();
#pragma unroll 8
        for (int d = 0; d < 64; d++)
            sPh[b * PH_STR + d * 4 + l] = __float2half(e_[d] * inv);
    }
    __syncthreads();

    // ---- phase 3: virt[b,c,l] = sum_d P[b,d,l] * v[d,c,l] (c-chunk 64) ----
    int tc = tid >> 4;
    float s4[4] = {0.f, 0.f, 0.f, 0.f};
    float q4[4] = {0.f, 0.f, 0.f, 0.f};
    for (int c0 = 0; c0 < NC; c0 += 64) {
#pragma unroll
        for (int j = 0; j < 16; j++) {
            int t  = tid + j * 256;
            int dd = t >> 6, cq = t & 63;
            *(float4*)&sV[dd * SV2_STR + cq * 4] =
                *(const float4*)(d_v + ((size_t)dd * NC + c0 + cq) * NL + lt);
        }
        __syncthreads();
        float a3[4][4][4];
#pragma unroll
        for (int i = 0; i < 4; i++)
#pragma unroll
            for (int j = 0; j < 4; j++)
#pragma unroll
                for (int l = 0; l < 4; l++) a3[i][j][l] = 0.f;
#pragma unroll 2
        for (int d = 0; d < 64; d++) {
            float4 p[4];
#pragma unroll
            for (int bi = 0; bi < 4; bi++) {
                uint2 ph = *(uint2*)&sPh[(tb + 16 * bi) * PH_STR + d * 4];
                float2 p01 = __half22float2(*(__half2*)&ph.x);
                float2 p23 = __half22float2(*(__half2*)&ph.y);
                p[bi] = make_float4(p01.x, p01.y, p23.x, p23.y);
            }
            float4 vv[4];
#pragma unroll
            for (int ci = 0; ci < 4; ci++)
                vv[ci] = *(float4*)&sV[d * SV2_STR + (tc + 16 * ci) * 4];
#pragma unroll
            for (int bi = 0; bi < 4; bi++)
#pragma unroll
                for (int ci = 0; ci < 4; ci++) {
                    a3[bi][ci][0] += p[bi].x * vv[ci].x;
                    a3[bi][ci][1] += p[bi].y * vv[ci].y;
                    a3[bi][ci][2] += p[bi].z * vv[ci].z;
                    a3[bi][ci][3] += p[bi].w * vv[ci].w;
                }
        }
#pragma unroll
        for (int bi = 0; bi < 4; bi++)
#pragma unroll
            for (int ci = 0; ci < 4; ci++) {
                float v0 = a3[bi][ci][0], v1 = a3[bi][ci][1];
                float v2 = a3[bi][ci][2], v3 = a3[bi][ci][3];
                s4[bi] += (v0 + v1) + (v2 + v3);
                q4[bi] += (v0 * v0 + v1 * v1) + (v2 * v2 + v3 * v3);
                uint2 u;
                *(__half2*)&u.x = __floats2half2_rn(v0, v1);
                *(__half2*)&u.y = __floats2half2_rn(v2, v3);
                int c = c0 + tc + 16 * ci;
                *(uint2*)(d_virt_h + ((size_t)(tb + 16 * bi) * NC + c) * NL + lt) = u;
            }
        __syncthreads();
    }

    // ---- fused GN stats: deterministic CTA reduction -> global partials ----
#pragma unroll
    for (int bi = 0; bi < 4; bi++) {
        s4[bi] += __shfl_xor_sync(0xffffffffu, s4[bi], 16);
        q4[bi] += __shfl_xor_sync(0xffffffffu, q4[bi], 16);
    }
    int wid = tid >> 5, lane = tid & 31;
    if (lane < 16) {
#pragma unroll
        for (int bi = 0; bi < 4; bi++) {
            sRS[wid * 64 + lane + 16 * bi] = s4[bi];
            sRQ[wid * 64 + lane + 16 * bi] = q4[bi];
        }
    }
    __syncthreads();
    if (tid < 64) {
        float s = 0.f, q = 0.f;
#pragma unroll
        for (int w2 = 0; w2 < 8; w2++) {
            s += sRS[w2 * 64 + tid];
            q += sRQ[w2 * 64 + tid];
        }
        d_pS[blockIdx.x * 64 + tid] = s;
        d_pQ[blockIdx.x * 64 + tid] = q;
    }
}

// ---------------- K3b: finish GN stats from per-CTA partials ----------------
__global__ void k3b() {
    int b = blockIdx.x, tid = threadIdx.x;   // 64 blocks x 256 threads
    float s = 0.f, q = 0.f;
    for (int j = tid; j < NL / LT; j += 256) {
        s += d_pS[j * 64 + b];
        q += d_pQ[j * 64 + b];
    }
    __shared__ float ss[256], sq[256];
    ss[tid] = s; sq[tid] = q;
    __syncthreads();
    for (int st = 128; st > 0; st >>= 1) {
        if (tid < st) { ss[tid] += ss[tid + st]; sq[tid] += sq[tid + st]; }
        __syncthreads();
    }
    if (tid == 0) {
        float N    = (float)(NC * NL);
        float mean = ss[0] / N;
        float var  = sq[0] / N - mean * mean;
        d_mean[b] = mean;
        d_rstd[b] = rsqrtf(var + 1e-5f);
    }
}

// ---------------- launch ----------------------------------------------------
extern "C" void kernel_launch(void* const* d_in, const int* in_sizes, int n_in,
                              void* d_out, int out_size) {
    const float* x     = (const float*)d_in[0];
    const float* Wq    = (const float*)d_in[1];
    const float* Wk    = (const float*)d_in[2];
    const float* Wv    = (const float*)d_in[3];
    const float* Wc    = (const float*)d_in[4];
    const float* Wout  = (const float*)d_in[5];
    const float* gamma = (const float*)d_in[6];
    const float* beta  = (const float*)d_in[7];
    float* out = (float*)d_out;

    cudaFuncSetAttribute(k2_attn, cudaFuncAttributeMaxDynamicSharedMemorySize, K2_SMEM);

    dim3 b16(16, 16);
    k0_M <<<dim3(16, 16), b16>>>(Wq, Wk);
    k0_W2<<<dim3(16, 16), b16>>>(Wout, Wc);
    kprep_Ah<<<512, 256>>>(Wv, Wout);
    kcvt_xh<<<65536, 256>>>(x);

    k_gemm<0><<<dim3(4, NL / 128, NB), 256>>>(nullptr);

    k2_attn<<<NL / LT, 256, K2_SMEM>>>(x);
    k3b<<<NB, 256>>>();
    kprep_act<<<65536, 256>>>(gamma, beta);

    k_gemm<1><<<dim3(2, NL / 128, NB), 256>>>(out);
}